// round 3
// baseline (speedup 1.0000x reference)
#include <cuda_runtime.h>
#include <math.h>

#define B_ 8
#define L_ 1024
#define D_ 512
#define H_ 8
#define DH_ 64
#define INNER_ 512
#define BH_ (B_*H_)

typedef unsigned long long ull;

// ---------------- packed f32x2 helpers (sm_103a FFMA2 path) ----------------
__device__ __forceinline__ ull pk2(float lo, float hi) {
    ull r; asm("mov.b64 %0, {%1, %2};" : "=l"(r) : "f"(lo), "f"(hi)); return r;
}
__device__ __forceinline__ void upk2(ull v, float& lo, float& hi) {
    asm("mov.b64 {%0, %1}, %2;" : "=f"(lo), "=f"(hi) : "l"(v));
}
__device__ __forceinline__ ull ffma2(ull a, ull b, ull c) {
    ull d; asm("fma.rn.f32x2 %0, %1, %2, %3;" : "=l"(d) : "l"(a), "l"(b), "l"(c)); return d;
}

// ---------------- scratch (device globals; no runtime allocation) ----------------
__device__ float g_xn [B_*L_*D_];
__device__ float g_pe [L_*D_];
__device__ float g_pos[H_*L_*DH_];
__device__ float g_q  [B_*H_*L_*DH_];
__device__ float g_k  [B_*H_*L_*DH_];    // later kplus = k+pos
__device__ float g_v  [B_*H_*L_*DH_];
__device__ float g_c  [B_*H_*L_];
__device__ float g_ctx[B_*L_*D_];

// ---------------- LayerNorm ----------------
__global__ void __launch_bounds__(128) ln_kernel(const float* __restrict__ x,
                                                 const float* __restrict__ gamma,
                                                 const float* __restrict__ beta)
{
    int row = blockIdx.x;
    int tid = threadIdx.x;
    const float4* xr = (const float4*)(x + (size_t)row * D_);
    float4 xv = xr[tid];
    float s  = xv.x + xv.y + xv.z + xv.w;
    float sq = xv.x*xv.x + xv.y*xv.y + xv.z*xv.z + xv.w*xv.w;
    #pragma unroll
    for (int o = 16; o > 0; o >>= 1) {
        s  += __shfl_xor_sync(0xffffffffu, s,  o);
        sq += __shfl_xor_sync(0xffffffffu, sq, o);
    }
    __shared__ float ss[4], ssq[4];
    int warp = tid >> 5, lane = tid & 31;
    if (lane == 0) { ss[warp] = s; ssq[warp] = sq; }
    __syncthreads();
    s  = ss[0] + ss[1] + ss[2] + ss[3];
    sq = ssq[0] + ssq[1] + ssq[2] + ssq[3];
    float mu   = s * (1.0f / D_);
    float var  = sq * (1.0f / D_) - mu * mu;
    float rstd = rsqrtf(var + 1e-5f);
    float4 g  = ((const float4*)gamma)[tid];
    float4 bb = ((const float4*)beta)[tid];
    float4 o;
    o.x = (xv.x - mu) * rstd * g.x + bb.x;
    o.y = (xv.y - mu) * rstd * g.y + bb.y;
    o.z = (xv.z - mu) * rstd * g.z + bb.z;
    o.w = (xv.w - mu) * rstd * g.w + bb.w;
    ((float4*)(g_xn + (size_t)row * D_))[tid] = o;
}

// ---------------- rel-pos sinusoid table pe[l][d] ----------------
__global__ void pe_kernel()
{
    int l = blockIdx.x;
    for (int d = threadIdx.x; d < D_; d += blockDim.x) {
        float freq  = __expf(-(float)(2 * d) * (9.210340371976184f / (float)D_));
        float angle = ((float)l - (float)d) * freq;
        double a = (double)angle;
        float val = ((d & 1) == 0) ? (float)cos(a) : (float)sin(a);
        g_pe[(size_t)l * D_ + d] = val;
    }
}

// ---------------- generic SGEMM: C = A @ W^T (+bias), 128x128x8, FFMA2 inner ----------------
template<int MODE>
__global__ void __launch_bounds__(256) gemm_kernel(const float* __restrict__ W,
                                                   const float* __restrict__ bias,
                                                   float* __restrict__ C,
                                                   int M, int N, int K)
{
    const float* A = (MODE == 1) ? g_pe : (MODE == 2) ? g_xn : g_ctx;

    __shared__ float As[8 * 132];
    __shared__ float Bs[8 * 132];
    int tid = threadIdx.x;
    int tx = tid & 15, ty = tid >> 4;
    int m0 = blockIdx.y * 128, n0 = blockIdx.x * 128;

    int la_row = tid >> 1;
    int la_k   = (tid & 1) * 4;
    const float* Aptr = A + (size_t)(m0 + la_row) * K + la_k;
    const float* Wptr = W + (size_t)(n0 + la_row) * K + la_k;

    ull acc2[8][4];
    #pragma unroll
    for (int i = 0; i < 8; i++)
        #pragma unroll
        for (int j = 0; j < 4; j++) acc2[i][j] = 0ULL;

    float4 a4 = *(const float4*)(Aptr);
    float4 w4 = *(const float4*)(Wptr);

    for (int kt = 0; kt < K; kt += 8) {
        __syncthreads();
        As[(la_k + 0) * 132 + la_row] = a4.x;
        As[(la_k + 1) * 132 + la_row] = a4.y;
        As[(la_k + 2) * 132 + la_row] = a4.z;
        As[(la_k + 3) * 132 + la_row] = a4.w;
        Bs[(la_k + 0) * 132 + la_row] = w4.x;
        Bs[(la_k + 1) * 132 + la_row] = w4.y;
        Bs[(la_k + 2) * 132 + la_row] = w4.z;
        Bs[(la_k + 3) * 132 + la_row] = w4.w;
        __syncthreads();
        if (kt + 8 < K) {
            a4 = *(const float4*)(Aptr + kt + 8);
            w4 = *(const float4*)(Wptr + kt + 8);
        }
        #pragma unroll
        for (int k = 0; k < 8; k++) {
            float4 a0 = *(const float4*)&As[k * 132 + ty * 8];
            float4 a1 = *(const float4*)&As[k * 132 + ty * 8 + 4];
            ulonglong2 b01 = *(const ulonglong2*)&Bs[k * 132 + tx * 8];
            ulonglong2 b23 = *(const ulonglong2*)&Bs[k * 132 + tx * 8 + 4];
            float a[8] = {a0.x, a0.y, a0.z, a0.w, a1.x, a1.y, a1.z, a1.w};
            #pragma unroll
            for (int i = 0; i < 8; i++) {
                ull av = pk2(a[i], a[i]);
                acc2[i][0] = ffma2(av, b01.x, acc2[i][0]);
                acc2[i][1] = ffma2(av, b01.y, acc2[i][1]);
                acc2[i][2] = ffma2(av, b23.x, acc2[i][2]);
                acc2[i][3] = ffma2(av, b23.y, acc2[i][3]);
            }
        }
    }

    float acc[8][8];
    #pragma unroll
    for (int i = 0; i < 8; i++)
        #pragma unroll
        for (int j = 0; j < 4; j++)
            upk2(acc2[i][j], acc[i][2*j], acc[i][2*j+1]);

    int n_base = n0 + tx * 8;
    if (MODE == 0) {
        float bb[8];
        #pragma unroll
        for (int j = 0; j < 8; j++) bb[j] = bias[n_base + j];
        #pragma unroll
        for (int i = 0; i < 8; i++) {
            int m = m0 + ty * 8 + i;
            float* p = C + (size_t)m * N + n_base;
            float4 s0 = {acc[i][0] + bb[0], acc[i][1] + bb[1], acc[i][2] + bb[2], acc[i][3] + bb[3]};
            float4 s1 = {acc[i][4] + bb[4], acc[i][5] + bb[5], acc[i][6] + bb[6], acc[i][7] + bb[7]};
            *(float4*)p = s0; *(float4*)(p + 4) = s1;
        }
    } else if (MODE == 1) {
        int h = n_base >> 6, dh0 = n_base & 63;
        #pragma unroll
        for (int i = 0; i < 8; i++) {
            int l = m0 + ty * 8 + i;
            float* p = g_pos + ((size_t)((h << 10) + l)) * DH_ + dh0;
            float4 s0 = {acc[i][0], acc[i][1], acc[i][2], acc[i][3]};
            float4 s1 = {acc[i][4], acc[i][5], acc[i][6], acc[i][7]};
            *(float4*)p = s0; *(float4*)(p + 4) = s1;
        }
    } else {
        int sel   = n_base >> 9;
        int inner = n_base & 511;
        int h = inner >> 6, dh0 = inner & 63;
        float* dst = (sel == 0) ? g_q : (sel == 1) ? g_k : g_v;
        float bb[8];
        #pragma unroll
        for (int j = 0; j < 8; j++) bb[j] = bias[n_base + j];
        #pragma unroll
        for (int i = 0; i < 8; i++) {
            int m = m0 + ty * 8 + i;
            int b = m >> 10, l = m & 1023;
            float* p = dst + ((size_t)(((b << 3) + h) << 10) + l) * DH_ + dh0;
            float4 s0 = {acc[i][0] + bb[0], acc[i][1] + bb[1], acc[i][2] + bb[2], acc[i][3] + bb[3]};
            float4 s1 = {acc[i][4] + bb[4], acc[i][5] + bb[5], acc[i][6] + bb[6], acc[i][7] + bb[7]};
            *(float4*)p = s0; *(float4*)(p + 4) = s1;
        }
    }
}

// ---------------- kplus = k + pos (in place); c = u.k + v.pos ----------------
__global__ void __launch_bounds__(256) kplusc_kernel(const float* __restrict__ u,
                                                     const float* __restrict__ v)
{
    int warp = threadIdx.x >> 5, lane = threadIdx.x & 31;
    int gw = blockIdx.x * 8 + warp;
    int bh = gw >> 10;
    int m  = gw & 1023;
    int h  = bh & 7;
    size_t base  = ((size_t)(bh << 10) + m) * DH_;
    size_t pbase = ((size_t)(h  << 10) + m) * DH_;
    float k0 = g_k[base + lane],       k1 = g_k[base + lane + 32];
    float p0 = g_pos[pbase + lane],    p1 = g_pos[pbase + lane + 32];
    g_k[base + lane]      = k0 + p0;
    g_k[base + lane + 32] = k1 + p1;
    float cp = u[h * DH_ + lane] * k0 + u[h * DH_ + lane + 32] * k1
             + v[h * DH_ + lane] * p0 + v[h * DH_ + lane + 32] * p1;
    #pragma unroll
    for (int o = 16; o > 0; o >>= 1) cp += __shfl_xor_sync(0xffffffffu, cp, o);
    if (lane == 0) g_c[gw] = cp;
}

// ---------------- flash attention with FFMA2 ----------------
// block = 256 threads (8 warps), tile 64 q x 64 k, Dh=64.
// smem:
//   q2_s : 64 rows x 64 dh, value duplicated into 64-bit (q,q)   32 KB
//   union: kp_s (transposed K, [dh][col], stride 66 floats, 16.9 KB)
//          p2_s (P duplicated (p,p), 64 x 64 ull, 32 KB)          32 KB
//   v_s  : 64 x 64 floats                                        16 KB
#define KP_STRIDE 66
#define FLASH_SMEM (32768 + 32768 + 16384)

__global__ void __launch_bounds__(256) flash_kernel()
{
    extern __shared__ char smraw[];
    ull*   q2_s = (ull*)smraw;                    // 4096 ull
    float* kp_s = (float*)(smraw + 32768);        // union with p2_s
    ull*   p2_s = (ull*)(smraw + 32768);
    float* v_s  = (float*)(smraw + 65536);

    int bh = blockIdx.y;
    int qt = blockIdx.x;
    int tid = threadIdx.x, warp = tid >> 5, lane = tid & 31;
    int r0 = warp * 8, c0 = lane * 2;
    int b = bh >> 3, h = bh & 7;

    // load q, store duplicated (q,q) pairs
    const float* qg = g_q + ((size_t)(bh << 10) + qt * 64) * DH_;
    #pragma unroll
    for (int i = 0; i < 4; i++) {
        int idx = tid + i * 256;
        int row = idx >> 4, col = (idx & 15) << 2;
        float4 qv = *(const float4*)&qg[row * 64 + col];
        ulonglong2 t0 = {pk2(qv.x, qv.x), pk2(qv.y, qv.y)};
        ulonglong2 t1 = {pk2(qv.z, qv.z), pk2(qv.w, qv.w)};
        *(ulonglong2*)&q2_s[row * 64 + col]     = t0;
        *(ulonglong2*)&q2_s[row * 64 + col + 2] = t1;
    }

    float mi[8], li[8];
    ull O2[8];
    #pragma unroll
    for (int r = 0; r < 8; r++) { mi[r] = -1e30f; li[r] = 0.0f; O2[r] = 0ULL; }

    for (int kt = 0; kt < 16; kt++) {
        __syncthreads();      // prior PV reads of p2/v done; q2 ready (kt==0)
        const float* kg = g_k + ((size_t)(bh << 10) + kt * 64) * DH_;
        const float* vg = g_v + ((size_t)(bh << 10) + kt * 64) * DH_;
        #pragma unroll
        for (int i = 0; i < 4; i++) {
            int idx = tid + i * 256;
            int row = idx >> 4, col = (idx & 15) << 2;
            float4 kk = *(const float4*)&kg[row * 64 + col];
            kp_s[(col + 0) * KP_STRIDE + row] = kk.x;
            kp_s[(col + 1) * KP_STRIDE + row] = kk.y;
            kp_s[(col + 2) * KP_STRIDE + row] = kk.z;
            kp_s[(col + 3) * KP_STRIDE + row] = kk.w;
            *(float4*)&v_s[row * 64 + col] = *(const float4*)&vg[row * 64 + col];
        }
        float c0v = g_c[(bh << 10) + kt * 64 + c0];
        float c1v = g_c[(bh << 10) + kt * 64 + c0 + 1];
        __syncthreads();

        ull S2[8];
        ull cinit = pk2(c0v, c1v);
        #pragma unroll
        for (int r = 0; r < 8; r++) S2[r] = cinit;

        // S += q @ kp^T  (packed over the 2 columns this lane owns)
        #pragma unroll 4
        for (int dh = 0; dh < 64; dh += 4) {
            ull kA = *(const ull*)&kp_s[(dh + 0) * KP_STRIDE + c0];
            ull kB = *(const ull*)&kp_s[(dh + 1) * KP_STRIDE + c0];
            ull kC = *(const ull*)&kp_s[(dh + 2) * KP_STRIDE + c0];
            ull kD = *(const ull*)&kp_s[(dh + 3) * KP_STRIDE + c0];
            #pragma unroll
            for (int r = 0; r < 8; r++) {
                ulonglong2 q01 = *(const ulonglong2*)&q2_s[(r0 + r) * 64 + dh];
                ulonglong2 q23 = *(const ulonglong2*)&q2_s[(r0 + r) * 64 + dh + 2];
                S2[r] = ffma2(q01.x, kA, S2[r]);
                S2[r] = ffma2(q01.y, kB, S2[r]);
                S2[r] = ffma2(q23.x, kC, S2[r]);
                S2[r] = ffma2(q23.y, kD, S2[r]);
            }
        }

        // online softmax (scale = 0.125)
        float P0[8], P1[8];
        #pragma unroll
        for (int r = 0; r < 8; r++) {
            float s0, s1; upk2(S2[r], s0, s1);
            s0 *= 0.125f; s1 *= 0.125f;
            float mx = fmaxf(s0, s1);
            #pragma unroll
            for (int o = 16; o > 0; o >>= 1) mx = fmaxf(mx, __shfl_xor_sync(0xffffffffu, mx, o));
            float mnew = fmaxf(mi[r], mx);
            float corr = __expf(mi[r] - mnew);
            float p0 = __expf(s0 - mnew), p1 = __expf(s1 - mnew);
            float ls = p0 + p1;
            #pragma unroll
            for (int o = 16; o > 0; o >>= 1) ls += __shfl_xor_sync(0xffffffffu, ls, o);
            li[r] = li[r] * corr + ls;
            mi[r] = mnew;
            O2[r] = ffma2(O2[r], pk2(corr, corr), 0ULL);
            P0[r] = p0; P1[r] = p1;
        }

        __syncthreads();      // all warps done reading kp_s; reuse region for P (dup)
        #pragma unroll
        for (int r = 0; r < 8; r++) {
            ulonglong2 pp = {pk2(P0[r], P0[r]), pk2(P1[r], P1[r])};
            *(ulonglong2*)&p2_s[(r0 + r) * 64 + c0] = pp;
        }
        __syncwarp();         // p2 rows are warp-private: warp-level visibility suffices

        // O += P @ V  (packed over the 2 dh columns this lane owns)
        #pragma unroll 4
        for (int m = 0; m < 64; m += 4) {
            ull vA = *(const ull*)&v_s[(m + 0) * 64 + c0];
            ull vB = *(const ull*)&v_s[(m + 1) * 64 + c0];
            ull vC = *(const ull*)&v_s[(m + 2) * 64 + c0];
            ull vD = *(const ull*)&v_s[(m + 3) * 64 + c0];
            #pragma unroll
            for (int r = 0; r < 8; r++) {
                ulonglong2 p01 = *(const ulonglong2*)&p2_s[(r0 + r) * 64 + m];
                ulonglong2 p23 = *(const ulonglong2*)&p2_s[(r0 + r) * 64 + m + 2];
                O2[r] = ffma2(p01.x, vA, O2[r]);
                O2[r] = ffma2(p01.y, vB, O2[r]);
                O2[r] = ffma2(p23.x, vC, O2[r]);
                O2[r] = ffma2(p23.y, vD, O2[r]);
            }
        }
    }

    #pragma unroll
    for (int r = 0; r < 8; r++) {
        float inv = 1.0f / li[r];
        int row = qt * 64 + r0 + r;
        float o0, o1; upk2(O2[r], o0, o1);
        float2 ov; ov.x = o0 * inv; ov.y = o1 * inv;
        *(float2*)&g_ctx[((size_t)(b << 10) + row) * D_ + h * DH_ + c0] = ov;
    }
}

// ---------------- launch ----------------
extern "C" void kernel_launch(void* const* d_in, const int* in_sizes, int n_in,
                              void* d_out, int out_size)
{
    const float* x      = (const float*)d_in[0];
    const float* gamma  = (const float*)d_in[1];
    const float* beta   = (const float*)d_in[2];
    const float* w_qkv  = (const float*)d_in[3];
    const float* b_qkv  = (const float*)d_in[4];
    const float* w_pos  = (const float*)d_in[5];
    const float* w_out  = (const float*)d_in[6];
    const float* b_out  = (const float*)d_in[7];
    const float* u_bias = (const float*)d_in[8];
    const float* v_bias = (const float*)d_in[9];
    float* out = (float*)d_out;

    cudaFuncSetAttribute(flash_kernel, cudaFuncAttributeMaxDynamicSharedMemorySize, FLASH_SMEM);

    ln_kernel<<<B_ * L_, 128>>>(x, gamma, beta);
    pe_kernel<<<L_, 256>>>();
    gemm_kernel<1><<<dim3(4, 8), 256>>>(w_pos, nullptr, nullptr, L_, INNER_, D_);
    gemm_kernel<2><<<dim3(12, 64), 256>>>(w_qkv, b_qkv, nullptr, B_ * L_, 3 * INNER_, D_);
    kplusc_kernel<<<(BH_ * L_) / 8, 256>>>(u_bias, v_bias);
    flash_kernel<<<dim3(16, BH_), 256, FLASH_SMEM>>>();
    gemm_kernel<0><<<dim3(4, 64), 256>>>(w_out, b_out, out, B_ * L_, D_, D_);
}

// round 5
// speedup vs baseline: 1.4887x; 1.4887x over previous
#include <cuda_runtime.h>
#include <cuda_bf16.h>
#include <math.h>
#include <stdint.h>

#define B_ 8
#define L_ 1024
#define D_ 512
#define H_ 8
#define DH_ 64
#define INNER_ 512
#define BH_ (B_*H_)
#define KBIG 1536            // 3 * 512 split segments
#define NCHUNK 24            // KBIG / 64

// ---------------- scratch (device globals; no runtime allocation) ----------------
__device__ float g_pos[H_*L_*DH_];
__device__ float g_q  [B_*H_*L_*DH_];
__device__ float g_k  [B_*H_*L_*DH_];    // later kplus = k+pos
__device__ float g_v  [B_*H_*L_*DH_];
__device__ float g_c  [B_*H_*L_];
// split-bf16 "big" operands: A layout [hi|hi|lo], B layout [hi|lo|hi]
__device__ __nv_bfloat16 g_xn_big [B_*L_*KBIG];
__device__ __nv_bfloat16 g_ctx_big[B_*L_*KBIG];
__device__ __nv_bfloat16 g_pe_big [L_*KBIG];
__device__ __nv_bfloat16 g_wqkv_big[3*INNER_*KBIG];
__device__ __nv_bfloat16 g_wpos_big[INNER_*KBIG];
__device__ __nv_bfloat16 g_wout_big[D_*KBIG];

// ---------------- PTX helpers (baseline ISA only — no 'a' features) ----------------
__device__ __forceinline__ uint32_t smem_u32(const void* p) {
    uint32_t a;
    asm("{ .reg .u64 t; cvta.to.shared.u64 t, %1; cvt.u32.u64 %0, t; }" : "=r"(a) : "l"(p));
    return a;
}
__device__ __forceinline__ void cp_async16(uint32_t dst, const void* src) {
    asm volatile("cp.async.cg.shared.global [%0], [%1], 16;" :: "r"(dst), "l"(src) : "memory");
}
__device__ __forceinline__ void cp_commit() {
    asm volatile("cp.async.commit_group;" ::: "memory");
}
template<int N>
__device__ __forceinline__ void cp_wait() {
    asm volatile("cp.async.wait_group %0;" :: "n"(N) : "memory");
}
__device__ __forceinline__ void ldm_x4(uint32_t& r0, uint32_t& r1, uint32_t& r2, uint32_t& r3,
                                       uint32_t addr) {
    asm volatile("ldmatrix.sync.aligned.m8n8.x4.shared.b16 {%0,%1,%2,%3}, [%4];"
                 : "=r"(r0), "=r"(r1), "=r"(r2), "=r"(r3) : "r"(addr));
}
__device__ __forceinline__ void mma_bf16(float* c, const uint32_t* a, const uint32_t* b) {
    asm volatile("mma.sync.aligned.m16n8k16.row.col.f32.bf16.bf16.f32 "
                 "{%0,%1,%2,%3}, {%4,%5,%6,%7}, {%8,%9}, {%0,%1,%2,%3};"
                 : "+f"(c[0]), "+f"(c[1]), "+f"(c[2]), "+f"(c[3])
                 : "r"(a[0]), "r"(a[1]), "r"(a[2]), "r"(a[3]), "r"(b[0]), "r"(b[1]));
}

// ---------------- split helpers ----------------
__device__ __forceinline__ void split_bf16(float x, __nv_bfloat16& hi, __nv_bfloat16& lo) {
    hi = __float2bfloat16(x);
    lo = __float2bfloat16(x - __bfloat162float(hi));
}

// ---------------- LayerNorm: writes split-bf16 A-layout directly ----------------
__global__ void __launch_bounds__(128) ln_kernel(const float* __restrict__ x,
                                                 const float* __restrict__ gamma,
                                                 const float* __restrict__ beta)
{
    int row = blockIdx.x;
    int tid = threadIdx.x;
    const float4* xr = (const float4*)(x + (size_t)row * D_);
    float4 xv = xr[tid];
    float s  = xv.x + xv.y + xv.z + xv.w;
    float sq = xv.x*xv.x + xv.y*xv.y + xv.z*xv.z + xv.w*xv.w;
    #pragma unroll
    for (int o = 16; o > 0; o >>= 1) {
        s  += __shfl_xor_sync(0xffffffffu, s,  o);
        sq += __shfl_xor_sync(0xffffffffu, sq, o);
    }
    __shared__ float ss[4], ssq[4];
    int warp = tid >> 5, lane = tid & 31;
    if (lane == 0) { ss[warp] = s; ssq[warp] = sq; }
    __syncthreads();
    s  = ss[0] + ss[1] + ss[2] + ss[3];
    sq = ssq[0] + ssq[1] + ssq[2] + ssq[3];
    float mu   = s * (1.0f / D_);
    float var  = sq * (1.0f / D_) - mu * mu;
    float rstd = rsqrtf(var + 1e-5f);
    float4 g  = ((const float4*)gamma)[tid];
    float4 bb = ((const float4*)beta)[tid];
    float o4[4];
    o4[0] = (xv.x - mu) * rstd * g.x + bb.x;
    o4[1] = (xv.y - mu) * rstd * g.y + bb.y;
    o4[2] = (xv.z - mu) * rstd * g.z + bb.z;
    o4[3] = (xv.w - mu) * rstd * g.w + bb.w;
    __nv_bfloat16* dst = g_xn_big + (size_t)row * KBIG + tid * 4;
    #pragma unroll
    for (int j = 0; j < 4; j++) {
        __nv_bfloat16 hi, lo; split_bf16(o4[j], hi, lo);
        dst[j] = hi; dst[512 + j] = hi; dst[1024 + j] = lo;
    }
}

// ---------------- rel-pos sinusoid table -> split-bf16 A-layout ----------------
__global__ void pe_kernel()
{
    int l = blockIdx.x;
    for (int d = threadIdx.x; d < D_; d += blockDim.x) {
        float freq  = __expf(-(float)(2 * d) * (9.210340371976184f / (float)D_));
        float angle = ((float)l - (float)d) * freq;
        double a = (double)angle;
        float val = ((d & 1) == 0) ? (float)cos(a) : (float)sin(a);
        __nv_bfloat16 hi, lo; split_bf16(val, hi, lo);
        __nv_bfloat16* dst = g_pe_big + (size_t)l * KBIG;
        dst[d] = hi; dst[512 + d] = hi; dst[1024 + d] = lo;
    }
}

// ---------------- weight conversion: B-layout [hi|lo|hi] ----------------
__global__ void convw_kernel(const float* __restrict__ w, __nv_bfloat16* __restrict__ big, int total)
{
    int idx = blockIdx.x * 256 + threadIdx.x;
    if (idx >= total) return;
    int n = idx >> 9, k = idx & 511;
    float x = w[idx];
    __nv_bfloat16 hi, lo; split_bf16(x, hi, lo);
    __nv_bfloat16* dst = big + (size_t)n * KBIG;
    dst[k] = hi; dst[512 + k] = lo; dst[1024 + k] = hi;
}

// ---------------- HMMA GEMM: C(M,N) = Abig(M,1536) @ Bbig(N,1536)^T ----------------
// 128x128 CTA tile, 256 threads = 8 warps (2 m x 4 n), warp tile 64x32.
// K-chunks of 64 bf16, cp.async double-buffered, smem stride 72 bf16 (conflict-free).
// MODE 0: out proj -> C + bias ; MODE 1: pos -> g_pos ; MODE 2: qkv -> g_q/g_k/g_v + bias
#define AST 72
#define CHUNK_ELEMS (128 * AST)                 // smem elems per operand buffer
#define GEMM_SMEM (4 * CHUNK_ELEMS * 2)         // bytes: A0,A1,B0,B1

template<int MODE>
__global__ void __launch_bounds__(256) hmma_gemm(const __nv_bfloat16* __restrict__ A,
                                                 const __nv_bfloat16* __restrict__ Bw,
                                                 const float* __restrict__ bias,
                                                 float* __restrict__ C)
{
    extern __shared__ __nv_bfloat16 smb[];
    __nv_bfloat16* As[2] = {smb,                  smb + CHUNK_ELEMS};
    __nv_bfloat16* Bs[2] = {smb + 2*CHUNK_ELEMS,  smb + 3*CHUNK_ELEMS};

    int t = threadIdx.x, lane = t & 31, wid = t >> 5;
    int wm = wid & 1, wn = wid >> 1;            // warp grid 2 x 4
    int m0 = blockIdx.y * 128, n0 = blockIdx.x * 128;

    // load geometry: i = t + 256*j -> row = i>>3 (0..127), c16 = i&7 (16B units)
    int lrow[4], lc16[4];
    #pragma unroll
    for (int j = 0; j < 4; j++) { int i = t + 256 * j; lrow[j] = i >> 3; lc16[j] = i & 7; }

    uint32_t sA[2], sB[2];
    sA[0] = smem_u32(As[0]); sA[1] = smem_u32(As[1]);
    sB[0] = smem_u32(Bs[0]); sB[1] = smem_u32(Bs[1]);

    // issue chunk 0
    #pragma unroll
    for (int j = 0; j < 4; j++) {
        cp_async16(sA[0] + (lrow[j] * AST + lc16[j] * 8) * 2,
                   A  + (size_t)(m0 + lrow[j]) * KBIG + lc16[j] * 8);
        cp_async16(sB[0] + (lrow[j] * AST + lc16[j] * 8) * 2,
                   Bw + (size_t)(n0 + lrow[j]) * KBIG + lc16[j] * 8);
    }
    cp_commit();

    float acc[4][4][4];
    #pragma unroll
    for (int i = 0; i < 4; i++)
        #pragma unroll
        for (int j = 0; j < 4; j++)
            #pragma unroll
            for (int c = 0; c < 4; c++) acc[i][j][c] = 0.0f;

    // ldmatrix lane address offsets (identical pattern for A and B)
    int frow = lane & 15;          // row within 16-row tile
    int fk8  = (lane >> 4) * 8;    // k offset 0 or 8

    for (int kc = 0; kc < NCHUNK; kc++) {
        int b = kc & 1;
        if (kc + 1 < NCHUNK) {
            int nb = b ^ 1;
            #pragma unroll
            for (int j = 0; j < 4; j++) {
                cp_async16(sA[nb] + (lrow[j] * AST + lc16[j] * 8) * 2,
                           A  + (size_t)(m0 + lrow[j]) * KBIG + (kc + 1) * 64 + lc16[j] * 8);
                cp_async16(sB[nb] + (lrow[j] * AST + lc16[j] * 8) * 2,
                           Bw + (size_t)(n0 + lrow[j]) * KBIG + (kc + 1) * 64 + lc16[j] * 8);
            }
            cp_commit();
            cp_wait<1>();
        } else {
            cp_wait<0>();
        }
        __syncthreads();

        #pragma unroll
        for (int ks = 0; ks < 4; ks++) {
            uint32_t aF[4][4];
            #pragma unroll
            for (int mt = 0; mt < 4; mt++) {
                uint32_t addr = sA[b] + ((wm * 64 + mt * 16 + frow) * AST + ks * 16 + fk8) * 2;
                ldm_x4(aF[mt][0], aF[mt][1], aF[mt][2], aF[mt][3], addr);
            }
            uint32_t bF[4][2];
            #pragma unroll
            for (int np = 0; np < 2; np++) {
                uint32_t r0, r1, r2, r3;
                uint32_t addr = sB[b] + ((wn * 32 + np * 16 + frow) * AST + ks * 16 + fk8) * 2;
                ldm_x4(r0, r1, r2, r3, addr);
                bF[np*2][0] = r0; bF[np*2][1] = r2;
                bF[np*2+1][0] = r1; bF[np*2+1][1] = r3;
            }
            #pragma unroll
            for (int mt = 0; mt < 4; mt++)
                #pragma unroll
                for (int nt = 0; nt < 4; nt++)
                    mma_bf16(acc[mt][nt], aF[mt], bF[nt]);
        }
        __syncthreads();
    }

    // epilogue: thread holds rows (m16 tile: r, r+8), col pairs
    int rr = lane >> 2, cc = (lane & 3) * 2;
    #pragma unroll
    for (int mt = 0; mt < 4; mt++) {
        #pragma unroll
        for (int half = 0; half < 2; half++) {
            int m = m0 + wm * 64 + mt * 16 + rr + half * 8;
            #pragma unroll
            for (int nt = 0; nt < 4; nt++) {
                int n = n0 + wn * 32 + nt * 8 + cc;
                float v0 = acc[mt][nt][half * 2 + 0];
                float v1 = acc[mt][nt][half * 2 + 1];
                if (MODE != 1) { v0 += bias[n]; v1 += bias[n + 1]; }
                float* p;
                if (MODE == 0) {
                    p = C + (size_t)m * D_ + n;
                } else if (MODE == 1) {
                    int hh = n >> 6, dh0 = n & 63;
                    p = g_pos + ((size_t)(hh << 10) + m) * DH_ + dh0;
                } else {
                    int sel = n >> 9, inner = n & 511;
                    int hh = inner >> 6, dh0 = inner & 63;
                    float* dst = (sel == 0) ? g_q : (sel == 1) ? g_k : g_v;
                    int bb = m >> 10, ll = m & 1023;
                    p = dst + ((size_t)(((bb << 3) + hh) << 10) + ll) * DH_ + dh0;
                }
                float2 s; s.x = v0; s.y = v1;
                *(float2*)p = s;
            }
        }
    }
}

// ---------------- kplus = k + pos (in place); c = u.k + v.pos ----------------
__global__ void __launch_bounds__(256) kplusc_kernel(const float* __restrict__ u,
                                                     const float* __restrict__ v)
{
    int warp = threadIdx.x >> 5, lane = threadIdx.x & 31;
    int gw = blockIdx.x * 8 + warp;
    int bh = gw >> 10;
    int m  = gw & 1023;
    int h  = bh & 7;
    size_t base  = ((size_t)(bh << 10) + m) * DH_;
    size_t pbase = ((size_t)(h  << 10) + m) * DH_;
    float k0 = g_k[base + lane],       k1 = g_k[base + lane + 32];
    float p0 = g_pos[pbase + lane],    p1 = g_pos[pbase + lane + 32];
    g_k[base + lane]      = k0 + p0;
    g_k[base + lane + 32] = k1 + p1;
    float cp = u[h * DH_ + lane] * k0 + u[h * DH_ + lane + 32] * k1
             + v[h * DH_ + lane] * p0 + v[h * DH_ + lane + 32] * p1;
    #pragma unroll
    for (int o = 16; o > 0; o >>= 1) cp += __shfl_xor_sync(0xffffffffu, cp, o);
    if (lane == 0) g_c[gw] = cp;
}

// ---------------- flash attention (fp32 FFMA, round-2 proven) ----------------
#define KP_STRIDE 66
#define FLASH_SMEM ((4096 + 64*KP_STRIDE + 4096) * 4)

__global__ void __launch_bounds__(256) flash_kernel()
{
    extern __shared__ float sm[];
    float* q_s  = sm;                         // 64*64
    float* kp_s = sm + 4096;                  // 64*66 transposed; reused as P
    float* v_s  = sm + 4096 + 64 * KP_STRIDE; // 64*64

    int bh = blockIdx.y;
    int qt = blockIdx.x;
    int tid = threadIdx.x, warp = tid >> 5, lane = tid & 31;
    int r0 = warp * 8, c0 = lane * 2;
    int b = bh >> 3, h = bh & 7;

    const float* qg = g_q + ((size_t)(bh << 10) + qt * 64) * DH_;
    #pragma unroll
    for (int i = 0; i < 4; i++) {
        int idx = tid + i * 256;
        int row = idx >> 4, col = (idx & 15) << 2;
        *(float4*)&q_s[row * 64 + col] = *(const float4*)&qg[row * 64 + col];
    }

    float mi[8], li[8], O[8][2];
    #pragma unroll
    for (int r = 0; r < 8; r++) { mi[r] = -1e30f; li[r] = 0.0f; O[r][0] = 0.0f; O[r][1] = 0.0f; }

    for (int kt = 0; kt < 16; kt++) {
        __syncthreads();
        const float* kg = g_k + ((size_t)(bh << 10) + kt * 64) * DH_;
        const float* vg = g_v + ((size_t)(bh << 10) + kt * 64) * DH_;
        #pragma unroll
        for (int i = 0; i < 4; i++) {
            int idx = tid + i * 256;
            int row = idx >> 4, col = (idx & 15) << 2;
            float4 kk = *(const float4*)&kg[row * 64 + col];
            kp_s[(col + 0) * KP_STRIDE + row] = kk.x;
            kp_s[(col + 1) * KP_STRIDE + row] = kk.y;
            kp_s[(col + 2) * KP_STRIDE + row] = kk.z;
            kp_s[(col + 3) * KP_STRIDE + row] = kk.w;
            *(float4*)&v_s[row * 64 + col] = *(const float4*)&vg[row * 64 + col];
        }
        float c0v = g_c[(bh << 10) + kt * 64 + c0];
        float c1v = g_c[(bh << 10) + kt * 64 + c0 + 1];
        __syncthreads();

        float S[8][2];
        #pragma unroll
        for (int r = 0; r < 8; r++) { S[r][0] = c0v; S[r][1] = c1v; }

        #pragma unroll 4
        for (int dh = 0; dh < 64; dh++) {
            float2 kpv = *(const float2*)&kp_s[dh * KP_STRIDE + c0];
            #pragma unroll
            for (int r = 0; r < 8; r++) {
                float qv = q_s[(r0 + r) * 64 + dh];
                S[r][0] += qv * kpv.x;
                S[r][1] += qv * kpv.y;
            }
        }

        #pragma unroll
        for (int r = 0; r < 8; r++) {
            float s0 = S[r][0] * 0.125f, s1 = S[r][1] * 0.125f;
            float mx = fmaxf(s0, s1);
            #pragma unroll
            for (int o = 16; o > 0; o >>= 1) mx = fmaxf(mx, __shfl_xor_sync(0xffffffffu, mx, o));
            float mnew = fmaxf(mi[r], mx);
            float corr = __expf(mi[r] - mnew);
            float p0 = __expf(s0 - mnew), p1 = __expf(s1 - mnew);
            float ls = p0 + p1;
            #pragma unroll
            for (int o = 16; o > 0; o >>= 1) ls += __shfl_xor_sync(0xffffffffu, ls, o);
            li[r] = li[r] * corr + ls;
            mi[r] = mnew;
            O[r][0] *= corr; O[r][1] *= corr;
            S[r][0] = p0; S[r][1] = p1;
        }

        __syncthreads();
        #pragma unroll
        for (int r = 0; r < 8; r++) {
            float2 pp; pp.x = S[r][0]; pp.y = S[r][1];
            *(float2*)&kp_s[(r0 + r) * KP_STRIDE + c0] = pp;
        }
        __syncthreads();

        #pragma unroll 4
        for (int m = 0; m < 64; m++) {
            float2 vv = *(const float2*)&v_s[m * 64 + c0];
            #pragma unroll
            for (int r = 0; r < 8; r++) {
                float p = kp_s[(r0 + r) * KP_STRIDE + m];
                O[r][0] += p * vv.x;
                O[r][1] += p * vv.y;
            }
        }
    }

    // epilogue: write ctx as split-bf16 A-layout [hi|hi|lo]
    #pragma unroll
    for (int r = 0; r < 8; r++) {
        float inv = 1.0f / li[r];
        int row = qt * 64 + r0 + r;
        float o0 = O[r][0] * inv, o1 = O[r][1] * inv;
        __nv_bfloat16 h0, l0, h1, l1;
        split_bf16(o0, h0, l0); split_bf16(o1, h1, l1);
        __nv_bfloat16* dst = g_ctx_big + ((size_t)(b << 10) + row) * KBIG + h * DH_ + c0;
        __nv_bfloat162 hh; hh.x = h0; hh.y = h1;
        __nv_bfloat162 ll; ll.x = l0; ll.y = l1;
        *(__nv_bfloat162*)(dst)        = hh;
        *(__nv_bfloat162*)(dst + 512)  = hh;
        *(__nv_bfloat162*)(dst + 1024) = ll;
    }
}

// ---------------- launch ----------------
extern "C" void kernel_launch(void* const* d_in, const int* in_sizes, int n_in,
                              void* d_out, int out_size)
{
    const float* x      = (const float*)d_in[0];
    const float* gamma  = (const float*)d_in[1];
    const float* beta   = (const float*)d_in[2];
    const float* w_qkv  = (const float*)d_in[3];
    const float* b_qkv  = (const float*)d_in[4];
    const float* w_pos  = (const float*)d_in[5];
    const float* w_out  = (const float*)d_in[6];
    const float* b_out  = (const float*)d_in[7];
    const float* u_bias = (const float*)d_in[8];
    const float* v_bias = (const float*)d_in[9];
    float* out = (float*)d_out;

    cudaFuncSetAttribute(flash_kernel, cudaFuncAttributeMaxDynamicSharedMemorySize, FLASH_SMEM);
    cudaFuncSetAttribute(hmma_gemm<0>, cudaFuncAttributeMaxDynamicSharedMemorySize, GEMM_SMEM);
    cudaFuncSetAttribute(hmma_gemm<1>, cudaFuncAttributeMaxDynamicSharedMemorySize, GEMM_SMEM);
    cudaFuncSetAttribute(hmma_gemm<2>, cudaFuncAttributeMaxDynamicSharedMemorySize, GEMM_SMEM);

    __nv_bfloat16 *wq_big, *wp_big, *wo_big, *xn_big, *pe_big, *ctx_big;
    cudaGetSymbolAddress((void**)&wq_big, g_wqkv_big);
    cudaGetSymbolAddress((void**)&wp_big, g_wpos_big);
    cudaGetSymbolAddress((void**)&wo_big, g_wout_big);
    cudaGetSymbolAddress((void**)&xn_big, g_xn_big);
    cudaGetSymbolAddress((void**)&pe_big, g_pe_big);
    cudaGetSymbolAddress((void**)&ctx_big, g_ctx_big);

    // 1. LayerNorm -> split bf16
    ln_kernel<<<B_ * L_, 128>>>(x, gamma, beta);
    // 2. sinusoid table -> split bf16
    pe_kernel<<<L_, 256>>>();
    // 3. weight conversions (B-layout)
    convw_kernel<<<(3 * INNER_ * D_ + 255) / 256, 256>>>(w_qkv, wq_big, 3 * INNER_ * D_);
    convw_kernel<<<(INNER_ * D_ + 255) / 256, 256>>>(w_pos, wp_big, INNER_ * D_);
    convw_kernel<<<(D_ * INNER_ + 255) / 256, 256>>>(w_out, wo_big, D_ * INNER_);
    // 4. pos = pe @ w_pos^T   (M=1024, N=512)
    hmma_gemm<1><<<dim3(4, 8), 256, GEMM_SMEM>>>(pe_big, wp_big, nullptr, nullptr);
    // 5. qkv = xn @ w_qkv^T + b (M=8192, N=1536) -> scatter q/k/v
    hmma_gemm<2><<<dim3(12, 64), 256, GEMM_SMEM>>>(xn_big, wq_big, b_qkv, nullptr);
    // 6. kplus = k + pos; c
    kplusc_kernel<<<(BH_ * L_) / 8, 256>>>(u_bias, v_bias);
    // 7. flash attention -> ctx (split bf16)
    flash_kernel<<<dim3(16, BH_), 256, FLASH_SMEM>>>();
    // 8. out = ctx @ w_out^T + b (M=8192, N=512)
    hmma_gemm<0><<<dim3(4, 64), 256, GEMM_SMEM>>>(ctx_big, wo_big, b_out, out);
}

// round 6
// speedup vs baseline: 2.2154x; 1.4881x over previous
#include <cuda_runtime.h>
#include <cuda_bf16.h>
#include <math.h>
#include <stdint.h>

#define B_ 8
#define L_ 1024
#define D_ 512
#define H_ 8
#define DH_ 64
#define INNER_ 512
#define BH_ (B_*H_)
#define KBIG 1536            // 3 * 512 split segments
#define NCHUNK 24            // KBIG / 64

// ---------------- scratch (device globals; no runtime allocation) ----------------
__device__ float g_pos[H_*L_*DH_];
__device__ float g_k  [B_*H_*L_*DH_];    // f32 k (pre pos-add)
__device__ float g_v  [B_*H_*L_*DH_];    // f32 v (pre transpose)
__device__ float g_c  [B_*H_*L_];
// split-bf16 "big" operands for projection GEMMs (K=1536)
__device__ __nv_bfloat16 g_xn_big [B_*L_*KBIG];
__device__ __nv_bfloat16 g_ctx_big[B_*L_*KBIG];
__device__ __nv_bfloat16 g_pe_big [L_*KBIG];
__device__ __nv_bfloat16 g_wqkv_big[3*INNER_*KBIG];
__device__ __nv_bfloat16 g_wpos_big[INNER_*KBIG];
__device__ __nv_bfloat16 g_wout_big[D_*KBIG];
// split-bf16 attention operands (K = 3*64 = 192)
__device__ __nv_bfloat16 g_q_big [BH_*L_*192];         // [bh][l][hi|hi|lo]
__device__ __nv_bfloat16 g_k_big [BH_*L_*192];         // [bh][m][hi|lo|hi] (k+pos)
__device__ __nv_bfloat16 g_vt_big[BH_*16*64*192];      // [bh*16+kt][dh][hi|lo|hi] over m

// ---------------- PTX helpers (baseline ISA only) ----------------
__device__ __forceinline__ uint32_t smem_u32(const void* p) {
    uint32_t a;
    asm("{ .reg .u64 t; cvta.to.shared.u64 t, %1; cvt.u32.u64 %0, t; }" : "=r"(a) : "l"(p));
    return a;
}
__device__ __forceinline__ void cp_async16(uint32_t dst, const void* src) {
    asm volatile("cp.async.cg.shared.global [%0], [%1], 16;" :: "r"(dst), "l"(src) : "memory");
}
__device__ __forceinline__ void cp_commit() {
    asm volatile("cp.async.commit_group;" ::: "memory");
}
template<int N>
__device__ __forceinline__ void cp_wait() {
    asm volatile("cp.async.wait_group %0;" :: "n"(N) : "memory");
}
__device__ __forceinline__ void ldm_x4(uint32_t& r0, uint32_t& r1, uint32_t& r2, uint32_t& r3,
                                       uint32_t addr) {
    asm volatile("ldmatrix.sync.aligned.m8n8.x4.shared.b16 {%0,%1,%2,%3}, [%4];"
                 : "=r"(r0), "=r"(r1), "=r"(r2), "=r"(r3) : "r"(addr));
}
__device__ __forceinline__ void mma_bf16(float* c, const uint32_t* a, const uint32_t* b) {
    asm volatile("mma.sync.aligned.m16n8k16.row.col.f32.bf16.bf16.f32 "
                 "{%0,%1,%2,%3}, {%4,%5,%6,%7}, {%8,%9}, {%0,%1,%2,%3};"
                 : "+f"(c[0]), "+f"(c[1]), "+f"(c[2]), "+f"(c[3])
                 : "r"(a[0]), "r"(a[1]), "r"(a[2]), "r"(a[3]), "r"(b[0]), "r"(b[1]));
}

// ---------------- split helpers ----------------
__device__ __forceinline__ void split_bf16(float x, __nv_bfloat16& hi, __nv_bfloat16& lo) {
    hi = __float2bfloat16(x);
    lo = __float2bfloat16(x - __bfloat162float(hi));
}
__device__ __forceinline__ uint32_t pkbf2(float a, float b) {
    __nv_bfloat162 h = __floats2bfloat162_rn(a, b);     // .x=a (low), .y=b (high)
    return *(uint32_t*)&h;
}

// ---------------- LayerNorm: writes split-bf16 A-layout directly ----------------
__global__ void __launch_bounds__(128) ln_kernel(const float* __restrict__ x,
                                                 const float* __restrict__ gamma,
                                                 const float* __restrict__ beta)
{
    int row = blockIdx.x;
    int tid = threadIdx.x;
    const float4* xr = (const float4*)(x + (size_t)row * D_);
    float4 xv = xr[tid];
    float s  = xv.x + xv.y + xv.z + xv.w;
    float sq = xv.x*xv.x + xv.y*xv.y + xv.z*xv.z + xv.w*xv.w;
    #pragma unroll
    for (int o = 16; o > 0; o >>= 1) {
        s  += __shfl_xor_sync(0xffffffffu, s,  o);
        sq += __shfl_xor_sync(0xffffffffu, sq, o);
    }
    __shared__ float ss[4], ssq[4];
    int warp = tid >> 5, lane = tid & 31;
    if (lane == 0) { ss[warp] = s; ssq[warp] = sq; }
    __syncthreads();
    s  = ss[0] + ss[1] + ss[2] + ss[3];
    sq = ssq[0] + ssq[1] + ssq[2] + ssq[3];
    float mu   = s * (1.0f / D_);
    float var  = sq * (1.0f / D_) - mu * mu;
    float rstd = rsqrtf(var + 1e-5f);
    float4 g  = ((const float4*)gamma)[tid];
    float4 bb = ((const float4*)beta)[tid];
    float o4[4];
    o4[0] = (xv.x - mu) * rstd * g.x + bb.x;
    o4[1] = (xv.y - mu) * rstd * g.y + bb.y;
    o4[2] = (xv.z - mu) * rstd * g.z + bb.z;
    o4[3] = (xv.w - mu) * rstd * g.w + bb.w;
    __nv_bfloat16* dst = g_xn_big + (size_t)row * KBIG + tid * 4;
    #pragma unroll
    for (int j = 0; j < 4; j++) {
        __nv_bfloat16 hi, lo; split_bf16(o4[j], hi, lo);
        dst[j] = hi; dst[512 + j] = hi; dst[1024 + j] = lo;
    }
}

// ---------------- rel-pos sinusoid table -> split-bf16 A-layout ----------------
__global__ void pe_kernel()
{
    int l = blockIdx.x;
    for (int d = threadIdx.x; d < D_; d += blockDim.x) {
        float freq  = __expf(-(float)(2 * d) * (9.210340371976184f / (float)D_));
        float angle = ((float)l - (float)d) * freq;
        double a = (double)angle;
        float val = ((d & 1) == 0) ? (float)cos(a) : (float)sin(a);
        __nv_bfloat16 hi, lo; split_bf16(val, hi, lo);
        __nv_bfloat16* dst = g_pe_big + (size_t)l * KBIG;
        dst[d] = hi; dst[512 + d] = hi; dst[1024 + d] = lo;
    }
}

// ---------------- weight conversion: B-layout [hi|lo|hi] ----------------
__global__ void convw_kernel(const float* __restrict__ w, __nv_bfloat16* __restrict__ big, int total)
{
    int idx = blockIdx.x * 256 + threadIdx.x;
    if (idx >= total) return;
    int n = idx >> 9, k = idx & 511;
    float x = w[idx];
    __nv_bfloat16 hi, lo; split_bf16(x, hi, lo);
    __nv_bfloat16* dst = big + (size_t)n * KBIG;
    dst[k] = hi; dst[512 + k] = lo; dst[1024 + k] = hi;
}

// ---------------- HMMA GEMM (round-5 verified): C = Abig @ Bbig^T ----------------
#define AST 72
#define CHUNK_ELEMS (128 * AST)
#define GEMM_SMEM (4 * CHUNK_ELEMS * 2)

template<int MODE>
__global__ void __launch_bounds__(256) hmma_gemm(const __nv_bfloat16* __restrict__ A,
                                                 const __nv_bfloat16* __restrict__ Bw,
                                                 const float* __restrict__ bias,
                                                 float* __restrict__ C)
{
    extern __shared__ __nv_bfloat16 smb[];
    __nv_bfloat16* As[2] = {smb,                  smb + CHUNK_ELEMS};
    __nv_bfloat16* Bs[2] = {smb + 2*CHUNK_ELEMS,  smb + 3*CHUNK_ELEMS};

    int t = threadIdx.x, lane = t & 31, wid = t >> 5;
    int wm = wid & 1, wn = wid >> 1;
    int m0 = blockIdx.y * 128, n0 = blockIdx.x * 128;

    int lrow[4], lc16[4];
    #pragma unroll
    for (int j = 0; j < 4; j++) { int i = t + 256 * j; lrow[j] = i >> 3; lc16[j] = i & 7; }

    uint32_t sA[2], sB[2];
    sA[0] = smem_u32(As[0]); sA[1] = smem_u32(As[1]);
    sB[0] = smem_u32(Bs[0]); sB[1] = smem_u32(Bs[1]);

    #pragma unroll
    for (int j = 0; j < 4; j++) {
        cp_async16(sA[0] + (lrow[j] * AST + lc16[j] * 8) * 2,
                   A  + (size_t)(m0 + lrow[j]) * KBIG + lc16[j] * 8);
        cp_async16(sB[0] + (lrow[j] * AST + lc16[j] * 8) * 2,
                   Bw + (size_t)(n0 + lrow[j]) * KBIG + lc16[j] * 8);
    }
    cp_commit();

    float acc[4][4][4];
    #pragma unroll
    for (int i = 0; i < 4; i++)
        #pragma unroll
        for (int j = 0; j < 4; j++)
            #pragma unroll
            for (int c = 0; c < 4; c++) acc[i][j][c] = 0.0f;

    int frow = lane & 15;
    int fk8  = (lane >> 4) * 8;

    for (int kc = 0; kc < NCHUNK; kc++) {
        int b = kc & 1;
        if (kc + 1 < NCHUNK) {
            int nb = b ^ 1;
            #pragma unroll
            for (int j = 0; j < 4; j++) {
                cp_async16(sA[nb] + (lrow[j] * AST + lc16[j] * 8) * 2,
                           A  + (size_t)(m0 + lrow[j]) * KBIG + (kc + 1) * 64 + lc16[j] * 8);
                cp_async16(sB[nb] + (lrow[j] * AST + lc16[j] * 8) * 2,
                           Bw + (size_t)(n0 + lrow[j]) * KBIG + (kc + 1) * 64 + lc16[j] * 8);
            }
            cp_commit();
            cp_wait<1>();
        } else {
            cp_wait<0>();
        }
        __syncthreads();

        #pragma unroll
        for (int ks = 0; ks < 4; ks++) {
            uint32_t aF[4][4];
            #pragma unroll
            for (int mt = 0; mt < 4; mt++) {
                uint32_t addr = sA[b] + ((wm * 64 + mt * 16 + frow) * AST + ks * 16 + fk8) * 2;
                ldm_x4(aF[mt][0], aF[mt][1], aF[mt][2], aF[mt][3], addr);
            }
            uint32_t bF[4][2];
            #pragma unroll
            for (int np = 0; np < 2; np++) {
                uint32_t r0, r1, r2, r3;
                uint32_t addr = sB[b] + ((wn * 32 + np * 16 + frow) * AST + ks * 16 + fk8) * 2;
                ldm_x4(r0, r1, r2, r3, addr);
                bF[np*2][0] = r0; bF[np*2][1] = r2;
                bF[np*2+1][0] = r1; bF[np*2+1][1] = r3;
            }
            #pragma unroll
            for (int mt = 0; mt < 4; mt++)
                #pragma unroll
                for (int nt = 0; nt < 4; nt++)
                    mma_bf16(acc[mt][nt], aF[mt], bF[nt]);
        }
        __syncthreads();
    }

    int rr = lane >> 2, cc = (lane & 3) * 2;
    #pragma unroll
    for (int mt = 0; mt < 4; mt++) {
        #pragma unroll
        for (int half = 0; half < 2; half++) {
            int m = m0 + wm * 64 + mt * 16 + rr + half * 8;
            #pragma unroll
            for (int nt = 0; nt < 4; nt++) {
                int n = n0 + wn * 32 + nt * 8 + cc;
                float v0 = acc[mt][nt][half * 2 + 0];
                float v1 = acc[mt][nt][half * 2 + 1];
                if (MODE != 1) { v0 += bias[n]; v1 += bias[n + 1]; }
                if (MODE == 0) {
                    float2 s; s.x = v0; s.y = v1;
                    *(float2*)(C + (size_t)m * D_ + n) = s;
                } else if (MODE == 1) {
                    int hh = n >> 6, dh0 = n & 63;
                    float2 s; s.x = v0; s.y = v1;
                    *(float2*)(g_pos + ((size_t)(hh << 10) + m) * DH_ + dh0) = s;
                } else {
                    int sel = n >> 9, inner = n & 511;
                    int hh = inner >> 6, dh0 = inner & 63;
                    int bb = m >> 10, ll = m & 1023;
                    if (sel == 0) {
                        // q: write split directly [hi|hi|lo] over 192
                        __nv_bfloat16 h0, l0, h1, l1;
                        split_bf16(v0, h0, l0); split_bf16(v1, h1, l1);
                        __nv_bfloat16* d = g_q_big
                            + ((size_t)(((bb << 3) + hh) << 10) + ll) * 192 + dh0;
                        __nv_bfloat162 hh2; hh2.x = h0; hh2.y = h1;
                        __nv_bfloat162 ll2; ll2.x = l0; ll2.y = l1;
                        *(__nv_bfloat162*)(d)       = hh2;
                        *(__nv_bfloat162*)(d + 64)  = hh2;
                        *(__nv_bfloat162*)(d + 128) = ll2;
                    } else {
                        float* dst = (sel == 1) ? g_k : g_v;
                        float2 s; s.x = v0; s.y = v1;
                        *(float2*)(dst + ((size_t)(((bb << 3) + hh) << 10) + ll) * DH_ + dh0) = s;
                    }
                }
            }
        }
    }
}

// ---------------- kplus = k + pos -> split k_big [hi|lo|hi]; c = u.k + v.pos ----------------
__global__ void __launch_bounds__(256) kplusc_kernel(const float* __restrict__ u,
                                                     const float* __restrict__ v)
{
    int warp = threadIdx.x >> 5, lane = threadIdx.x & 31;
    int gw = blockIdx.x * 8 + warp;
    int bh = gw >> 10;
    int m  = gw & 1023;
    int h  = bh & 7;
    size_t base  = ((size_t)(bh << 10) + m) * DH_;
    size_t pbase = ((size_t)(h  << 10) + m) * DH_;
    float k0 = g_k[base + lane],       k1 = g_k[base + lane + 32];
    float p0 = g_pos[pbase + lane],    p1 = g_pos[pbase + lane + 32];
    float kp0 = k0 + p0, kp1 = k1 + p1;
    __nv_bfloat16 h0, l0, h1, l1;
    split_bf16(kp0, h0, l0); split_bf16(kp1, h1, l1);
    __nv_bfloat16* dst = g_k_big + (size_t)gw * 192;
    dst[lane] = h0;        dst[lane + 32] = h1;
    dst[64 + lane] = l0;   dst[64 + lane + 32] = l1;
    dst[128 + lane] = h0;  dst[128 + lane + 32] = h1;
    float cp = u[h * DH_ + lane] * k0 + u[h * DH_ + lane + 32] * k1
             + v[h * DH_ + lane] * p0 + v[h * DH_ + lane + 32] * p1;
    #pragma unroll
    for (int o = 16; o > 0; o >>= 1) cp += __shfl_xor_sync(0xffffffffu, cp, o);
    if (lane == 0) g_c[gw] = cp;
}

// ---------------- v transpose -> vt_big [dh][hi|lo|hi over m] per 64-tile ----------------
__global__ void __launch_bounds__(256) vtrans_kernel()
{
    int tile = blockIdx.x;               // bh*16 + kt
    int bh = tile >> 4, kt = tile & 15;
    __shared__ float ts[64 * 65];
    int t = threadIdx.x;
    const float* vg = g_v + ((size_t)(bh << 10) + kt * 64) * DH_;
    #pragma unroll
    for (int j = 0; j < 16; j++) {
        int i = t + 256 * j;
        int r = i >> 6, d = i & 63;
        ts[d * 65 + r] = vg[r * 64 + d];
    }
    __syncthreads();
    __nv_bfloat16* dst = g_vt_big + (size_t)tile * 64 * 192;
    #pragma unroll
    for (int j = 0; j < 16; j++) {
        int i = t + 256 * j;
        int d = i >> 6, m = i & 63;
        float x = ts[d * 65 + m];
        __nv_bfloat16 hi, lo; split_bf16(x, hi, lo);
        dst[d * 192 + m] = hi;
        dst[d * 192 + 64 + m] = lo;
        dst[d * 192 + 128 + m] = hi;
    }
}

// ---------------- HMMA flash attention ----------------
// block = 256 thr (8 warps x 16 q-rows = 128 q rows), k-tiles of 64, Dh=64.
// QK: K=192 split [qhi|qhi|qlo]x[khi|klo|khi]. PV: register P split, V^T [vhi|vlo|vhi].
#define FAST 200                         // padded bf16 stride (400B = conflict-free ldmatrix)
#define FK_OFF (128 * FAST)
#define FV_OFF (FK_OFF + 2 * 64 * FAST)
#define FLASH_SMEM ((128 * FAST + 4 * 64 * FAST) * 2)

__global__ void __launch_bounds__(256) flash_hmma()
{
    extern __shared__ __nv_bfloat16 fsm[];
    __nv_bfloat16* q_s = fsm;
    uint32_t sq = smem_u32(q_s);
    uint32_t sk[2] = {smem_u32(fsm + FK_OFF), smem_u32(fsm + FK_OFF + 64 * FAST)};
    uint32_t svv[2] = {smem_u32(fsm + FV_OFF), smem_u32(fsm + FV_OFF + 64 * FAST)};

    int bh = blockIdx.y, qt = blockIdx.x;
    int t = threadIdx.x, lane = t & 31, wid = t >> 5;
    int frow = lane & 15, fk8 = (lane >> 4) * 8;
    int gr = lane >> 2, ct2 = (lane & 3) * 2;

    const __nv_bfloat16* qg = g_q_big + ((size_t)(bh << 10) + qt * 128) * 192;
    const __nv_bfloat16* kg = g_k_big + ((size_t)(bh << 10)) * 192;
    const __nv_bfloat16* vg = g_vt_big + (size_t)(bh * 16) * 64 * 192;

    // q tile (group 0)
    #pragma unroll
    for (int j = 0; j < 12; j++) {
        int i = t + 256 * j;
        int r = i / 24, c = i % 24;
        cp_async16(sq + (r * FAST + c * 8) * 2, qg + (size_t)r * 192 + c * 8);
    }
    // k/v tile 0 (same group)
    #pragma unroll
    for (int j = 0; j < 6; j++) {
        int i = t + 256 * j;
        int r = i / 24, c = i % 24;
        cp_async16(sk[0] + (r * FAST + c * 8) * 2, kg + (size_t)r * 192 + c * 8);
        cp_async16(svv[0] + (r * FAST + c * 8) * 2, vg + (size_t)r * 192 + c * 8);
    }
    cp_commit();

    float O[8][4];
    #pragma unroll
    for (int nt = 0; nt < 8; nt++)
        #pragma unroll
        for (int j = 0; j < 4; j++) O[nt][j] = 0.0f;
    float mi0 = -1e30f, mi1 = -1e30f, li0 = 0.0f, li1 = 0.0f;

    for (int kt = 0; kt < 16; kt++) {
        int b = kt & 1;
        if (kt + 1 < 16) {
            int nb = b ^ 1;
            #pragma unroll
            for (int j = 0; j < 6; j++) {
                int i = t + 256 * j;
                int r = i / 24, c = i % 24;
                cp_async16(sk[nb] + (r * FAST + c * 8) * 2,
                           kg + (size_t)((kt + 1) * 64 + r) * 192 + c * 8);
                cp_async16(svv[nb] + (r * FAST + c * 8) * 2,
                           vg + ((size_t)(kt + 1) * 64 + r) * 192 + c * 8);
            }
            cp_commit();
            cp_wait<1>();
        } else {
            cp_wait<0>();
        }
        __syncthreads();

        // ---- QK: S(16x64) = q(16x192) @ k(64x192)^T ----
        float S[8][4];
        #pragma unroll
        for (int nt = 0; nt < 8; nt++)
            #pragma unroll
            for (int j = 0; j < 4; j++) S[nt][j] = 0.0f;

        #pragma unroll
        for (int ks = 0; ks < 12; ks++) {
            uint32_t aF[4];
            ldm_x4(aF[0], aF[1], aF[2], aF[3],
                   sq + ((wid * 16 + frow) * FAST + ks * 16 + fk8) * 2);
            uint32_t bF[8][2];
            #pragma unroll
            for (int np = 0; np < 4; np++) {
                uint32_t r0, r1, r2, r3;
                ldm_x4(r0, r1, r2, r3,
                       sk[b] + ((np * 16 + frow) * FAST + ks * 16 + fk8) * 2);
                bF[np*2][0] = r0; bF[np*2][1] = r2;
                bF[np*2+1][0] = r1; bF[np*2+1][1] = r3;
            }
            #pragma unroll
            for (int nt = 0; nt < 8; nt++) mma_bf16(S[nt], aF, bF[nt]);
        }

        // ---- softmax (two row-halves: gr and gr+8) ----
        int cbase = (bh << 10) + kt * 64;
        float corr0, corr1;
        {
            float sv0[8][2], sv1[8][2];
            float mx0 = -1e30f, mx1 = -1e30f;
            #pragma unroll
            for (int nt = 0; nt < 8; nt++) {
                float cb0 = __ldg(&g_c[cbase + nt * 8 + ct2]);
                float cb1 = __ldg(&g_c[cbase + nt * 8 + ct2 + 1]);
                sv0[nt][0] = (S[nt][0] + cb0) * 0.125f;
                sv0[nt][1] = (S[nt][1] + cb1) * 0.125f;
                sv1[nt][0] = (S[nt][2] + cb0) * 0.125f;
                sv1[nt][1] = (S[nt][3] + cb1) * 0.125f;
                mx0 = fmaxf(mx0, fmaxf(sv0[nt][0], sv0[nt][1]));
                mx1 = fmaxf(mx1, fmaxf(sv1[nt][0], sv1[nt][1]));
            }
            mx0 = fmaxf(mx0, __shfl_xor_sync(0xffffffffu, mx0, 1));
            mx0 = fmaxf(mx0, __shfl_xor_sync(0xffffffffu, mx0, 2));
            mx1 = fmaxf(mx1, __shfl_xor_sync(0xffffffffu, mx1, 1));
            mx1 = fmaxf(mx1, __shfl_xor_sync(0xffffffffu, mx1, 2));
            float mn0 = fmaxf(mi0, mx0), mn1 = fmaxf(mi1, mx1);
            corr0 = __expf(mi0 - mn0); corr1 = __expf(mi1 - mn1);
            float ls0 = 0.0f, ls1 = 0.0f;
            #pragma unroll
            for (int nt = 0; nt < 8; nt++) {
                S[nt][0] = __expf(sv0[nt][0] - mn0); ls0 += S[nt][0];
                S[nt][1] = __expf(sv0[nt][1] - mn0); ls0 += S[nt][1];
                S[nt][2] = __expf(sv1[nt][0] - mn1); ls1 += S[nt][2];
                S[nt][3] = __expf(sv1[nt][1] - mn1); ls1 += S[nt][3];
            }
            ls0 += __shfl_xor_sync(0xffffffffu, ls0, 1);
            ls0 += __shfl_xor_sync(0xffffffffu, ls0, 2);
            ls1 += __shfl_xor_sync(0xffffffffu, ls1, 1);
            ls1 += __shfl_xor_sync(0xffffffffu, ls1, 2);
            li0 = li0 * corr0 + ls0; mi0 = mn0;
            li1 = li1 * corr1 + ls1; mi1 = mn1;
        }
        #pragma unroll
        for (int nt = 0; nt < 8; nt++) {
            O[nt][0] *= corr0; O[nt][1] *= corr0;
            O[nt][2] *= corr1; O[nt][3] *= corr1;
        }

        // ---- register P -> A-fragments (hi + lo split) ----
        uint32_t phi[4][4], plo[4][4];
        #pragma unroll
        for (int ks2 = 0; ks2 < 4; ks2++) {
            int n0t = 2 * ks2, n1t = n0t + 1;
            #pragma unroll
            for (int q = 0; q < 2; q++) {       // q=0: nt even, q=1: nt odd
                int nt = q ? n1t : n0t;
                #pragma unroll
                for (int hrow = 0; hrow < 2; hrow++) {
                    float p0 = S[nt][hrow * 2 + 0];
                    float p1 = S[nt][hrow * 2 + 1];
                    __nv_bfloat16 h0 = __float2bfloat16(p0);
                    __nv_bfloat16 h1 = __float2bfloat16(p1);
                    float r0f = p0 - __bfloat162float(h0);
                    float r1f = p1 - __bfloat162float(h1);
                    __nv_bfloat162 hp; hp.x = h0; hp.y = h1;
                    phi[ks2][q * 2 + hrow] = *(uint32_t*)&hp;
                    plo[ks2][q * 2 + hrow] = pkbf2(r0f, r1f);
                }
            }
        }

        // ---- PV: O(16x64) += P(16x192 split) @ Vt(64x192 split)^T ----
        #pragma unroll
        for (int ks = 0; ks < 12; ks++) {
            const uint32_t* aP = (ks < 8) ? phi[ks & 3] : plo[ks & 3];
            uint32_t bF[8][2];
            #pragma unroll
            for (int np = 0; np < 4; np++) {
                uint32_t r0, r1, r2, r3;
                ldm_x4(r0, r1, r2, r3,
                       svv[b] + ((np * 16 + frow) * FAST + ks * 16 + fk8) * 2);
                bF[np*2][0] = r0; bF[np*2][1] = r2;
                bF[np*2+1][0] = r1; bF[np*2+1][1] = r3;
            }
            #pragma unroll
            for (int nt = 0; nt < 8; nt++) mma_bf16(O[nt], aP, bF[nt]);
        }
        __syncthreads();
    }

    // ---- epilogue: O/li -> ctx split [hi|hi|lo] ----
    float inv0 = 1.0f / li0, inv1 = 1.0f / li1;
    int bb = bh >> 3, hh = bh & 7;
    int l0 = qt * 128 + wid * 16 + gr;
    int l1 = l0 + 8;
    #pragma unroll
    for (int nt = 0; nt < 8; nt++) {
        int dh = nt * 8 + ct2;
        float o00 = O[nt][0] * inv0, o01 = O[nt][1] * inv0;
        float o10 = O[nt][2] * inv1, o11 = O[nt][3] * inv1;
        __nv_bfloat16 a0, b0, a1, b1;
        split_bf16(o00, a0, b0); split_bf16(o01, a1, b1);
        __nv_bfloat16* d0 = g_ctx_big + ((size_t)(bb << 10) + l0) * KBIG + hh * DH_ + dh;
        __nv_bfloat162 hp; hp.x = a0; hp.y = a1;
        __nv_bfloat162 lp; lp.x = b0; lp.y = b1;
        *(__nv_bfloat162*)(d0)        = hp;
        *(__nv_bfloat162*)(d0 + 512)  = hp;
        *(__nv_bfloat162*)(d0 + 1024) = lp;
        split_bf16(o10, a0, b0); split_bf16(o11, a1, b1);
        __nv_bfloat16* d1 = g_ctx_big + ((size_t)(bb << 10) + l1) * KBIG + hh * DH_ + dh;
        hp.x = a0; hp.y = a1; lp.x = b0; lp.y = b1;
        *(__nv_bfloat162*)(d1)        = hp;
        *(__nv_bfloat162*)(d1 + 512)  = hp;
        *(__nv_bfloat162*)(d1 + 1024) = lp;
    }
}

// ---------------- launch ----------------
extern "C" void kernel_launch(void* const* d_in, const int* in_sizes, int n_in,
                              void* d_out, int out_size)
{
    const float* x      = (const float*)d_in[0];
    const float* gamma  = (const float*)d_in[1];
    const float* beta   = (const float*)d_in[2];
    const float* w_qkv  = (const float*)d_in[3];
    const float* b_qkv  = (const float*)d_in[4];
    const float* w_pos  = (const float*)d_in[5];
    const float* w_out  = (const float*)d_in[6];
    const float* b_out  = (const float*)d_in[7];
    const float* u_bias = (const float*)d_in[8];
    const float* v_bias = (const float*)d_in[9];
    float* out = (float*)d_out;

    cudaFuncSetAttribute(flash_hmma, cudaFuncAttributeMaxDynamicSharedMemorySize, FLASH_SMEM);
    cudaFuncSetAttribute(hmma_gemm<0>, cudaFuncAttributeMaxDynamicSharedMemorySize, GEMM_SMEM);
    cudaFuncSetAttribute(hmma_gemm<1>, cudaFuncAttributeMaxDynamicSharedMemorySize, GEMM_SMEM);
    cudaFuncSetAttribute(hmma_gemm<2>, cudaFuncAttributeMaxDynamicSharedMemorySize, GEMM_SMEM);

    __nv_bfloat16 *wq_big, *wp_big, *wo_big, *xn_big, *pe_big, *ctx_big;
    cudaGetSymbolAddress((void**)&wq_big, g_wqkv_big);
    cudaGetSymbolAddress((void**)&wp_big, g_wpos_big);
    cudaGetSymbolAddress((void**)&wo_big, g_wout_big);
    cudaGetSymbolAddress((void**)&xn_big, g_xn_big);
    cudaGetSymbolAddress((void**)&pe_big, g_pe_big);
    cudaGetSymbolAddress((void**)&ctx_big, g_ctx_big);

    // 1. LayerNorm -> split bf16
    ln_kernel<<<B_ * L_, 128>>>(x, gamma, beta);
    // 2. sinusoid table -> split bf16
    pe_kernel<<<L_, 256>>>();
    // 3. weight conversions
    convw_kernel<<<(3 * INNER_ * D_ + 255) / 256, 256>>>(w_qkv, wq_big, 3 * INNER_ * D_);
    convw_kernel<<<(INNER_ * D_ + 255) / 256, 256>>>(w_pos, wp_big, INNER_ * D_);
    convw_kernel<<<(D_ * INNER_ + 255) / 256, 256>>>(w_out, wo_big, D_ * INNER_);
    // 4. pos = pe @ w_pos^T
    hmma_gemm<1><<<dim3(4, 8), 256, GEMM_SMEM>>>(pe_big, wp_big, nullptr, nullptr);
    // 5. qkv (q written split, k/v f32)
    hmma_gemm<2><<<dim3(12, 64), 256, GEMM_SMEM>>>(xn_big, wq_big, b_qkv, nullptr);
    // 6. kplus -> k_big split; c
    kplusc_kernel<<<(BH_ * L_) / 8, 256>>>(u_bias, v_bias);
    // 7. v transpose -> vt_big split
    vtrans_kernel<<<BH_ * 16, 256>>>();
    // 8. HMMA flash attention -> ctx split
    flash_hmma<<<dim3(8, BH_), 256, FLASH_SMEM>>>();
    // 9. out = ctx @ w_out^T + b
    hmma_gemm<0><<<dim3(4, 64), 256, GEMM_SMEM>>>(ctx_big, wo_big, b_out, out);
}